// round 12
// baseline (speedup 1.0000x reference)
#include <cuda_runtime.h>
#include <cuda_bf16.h>
#include <cuda_fp16.h>
#include <cstdint>

// Problem dims (fixed by the reference)
#define B_      4
#define S_      2048
#define D_      4096
#define O_      4096
#define M_      8192
#define TOPK_   2048
#define NMASKS_ 100

// ---------------------------------------------------------------------------
// Static device scratch (no runtime allocation allowed)
// ---------------------------------------------------------------------------
__device__ float g_psum[8][D_];
__device__ unsigned char g_amask[D_];
__device__ int g_counts[NMASKS_];
__device__ __align__(16) __half g_xh[(size_t)M_ * D_];   // fp16(x)
__device__ __align__(16) __half g_wh[(size_t)O_ * D_];   // fp16(weff)

// ---------------------------------------------------------------------------
// K1: partial column sums of x[0, 0..pb, :] over 8 row chunks
// grid (32, 8), 128 threads. y==0 zeroes g_amask; (0,0) zeroes g_counts.
// ---------------------------------------------------------------------------
__global__ void mean_p1(const float* __restrict__ x, const int* __restrict__ pb)
{
    const int d = blockIdx.x * 128 + threadIdx.x;
    if (blockIdx.y == 0) {
        g_amask[d] = 0;
        if (blockIdx.x == 0 && threadIdx.x < NMASKS_) g_counts[threadIdx.x] = 0;
    }
    const int rows  = pb[0] + 1;
    const int chunk = (rows + 7) / 8;
    const int r0 = blockIdx.y * chunk;
    const int r1 = (r0 + chunk < rows) ? (r0 + chunk) : rows;
    float s = 0.f;
    int r = r0;
    for (; r + 4 <= r1; r += 4) {
        s += x[(size_t)(r + 0) * D_ + d];
        s += x[(size_t)(r + 1) * D_ + d];
        s += x[(size_t)(r + 2) * D_ + d];
        s += x[(size_t)(r + 3) * D_ + d];
    }
    for (; r < r1; ++r) s += x[(size_t)r * D_ + d];
    g_psum[blockIdx.y][d] = s;
}

// ---------------------------------------------------------------------------
// K2: reduce partials -> f, exact top-k rank, scatter via perm, AND
//     accumulate per-block partial overlap counts into g_counts.
// 32 blocks x 512 threads.
// ---------------------------------------------------------------------------
__global__ void rank_kernel(const int* __restrict__ perm, const int* __restrict__ pb,
                            const unsigned char* __restrict__ stored)
{
    __shared__ unsigned int keys[D_];
    __shared__ int sr[128][4];
    __shared__ int spos[128];
    __shared__ int ssel[128];

    const int t = threadIdx.x;
    const int rows = pb[0] + 1;

    for (int j = t; j < D_; j += 512) {
        float s = 0.f;
        #pragma unroll
        for (int y = 0; y < 8; ++y) s += g_psum[y][j];
        keys[j] = __float_as_uint(fabsf(s / (float)rows));
    }
    __syncthreads();

    const int jl = t & 127;
    const int h  = t >> 7;                       // 0..3
    const int j  = blockIdx.x * 128 + jl;
    const unsigned int kj = keys[j];
    int r = 0;
    const int i0 = h * 1024;
    #pragma unroll 8
    for (int i = i0; i < i0 + 1024; ++i) {
        const unsigned int ki = keys[i];
        r += (ki > kj) || (ki == kj && i < j);
    }
    sr[jl][h] = r;
    __syncthreads();

    if (t < 128) {
        const int rank = sr[t][0] + sr[t][1] + sr[t][2] + sr[t][3];
        const int pos  = perm[blockIdx.x * 128 + t];
        const int sel  = (rank < TOPK_) ? 1 : 0;
        spos[t] = pos;
        ssel[t] = sel;
        if (sel) g_amask[pos] = 1;               // perm: no conflicts
    }
    __syncthreads();

    const int warp = t >> 5, lane = t & 31;
    for (int m = warp; m < NMASKS_; m += 16) {
        const unsigned char* row = stored + (size_t)m * D_;
        int c = 0;
        #pragma unroll
        for (int i = lane; i < 128; i += 32)
            c += ssel[i] ? (int)row[spos[i]] : 0;
        #pragma unroll
        for (int o = 16; o > 0; o >>= 1) c += __shfl_down_sync(0xffffffffu, c, o);
        if (lane == 0) atomicAdd(&g_counts[m], c);
    }
}

// ---------------------------------------------------------------------------
// K3 (merged): blocks [0, 16384)      -> x -> fp16
//              blocks [16384, 24576)  -> weff = w + gate*mask*wn -> fp16
// ---------------------------------------------------------------------------
#define XBLKS_ ((int)(((size_t)M_ * D_ / 8) / 256))   // 16384
#define WBLKS_ ((int)(((size_t)O_ * D_ / 8) / 256))   // 8192

__global__ void split_kernel(const float* __restrict__ x,
                             const float* __restrict__ w,
                             const float* __restrict__ wn,
                             const unsigned char* __restrict__ stored)
{
    if (blockIdx.x < XBLKS_) {
        size_t i = ((size_t)blockIdx.x * 256 + threadIdx.x) * 8;
        float4 v0 = *(const float4*)(x + i);
        float4 v1 = *(const float4*)(x + i + 4);
        float v[8] = {v0.x, v0.y, v0.z, v0.w, v1.x, v1.y, v1.z, v1.w};
        __align__(16) __half h[8];
        #pragma unroll
        for (int j = 0; j < 8; ++j) h[j] = __float2half(v[j]);
        *(uint4*)(g_xh + i) = *(uint4*)h;
    } else {
        __shared__ int smax[8];
        __shared__ int s_best;
        const int t = threadIdx.x;
        int v = 0;
        if (t < NMASKS_) v = (g_counts[t] << 7) | (127 - t);
        #pragma unroll
        for (int o = 16; o > 0; o >>= 1) v = max(v, __shfl_down_sync(0xffffffffu, v, o));
        if ((t & 31) == 0) smax[t >> 5] = v;
        __syncthreads();
        if (t == 0) {
            int b = smax[0];
            #pragma unroll
            for (int q = 1; q < 8; ++q) b = max(b, smax[q]);
            s_best = b;
        }
        __syncthreads();
        const int best = s_best;
        const int gate = ((best >> 7) >= 1229);   // count/2048 >= float32(0.6)
        const unsigned char* brow = stored + (size_t)(127 - (best & 127)) * D_;

        size_t i = ((size_t)(blockIdx.x - XBLKS_) * 256 + t) * 8;
        const int dbase = (int)(i & (size_t)(D_ - 1));
        uint2 bb = *(const uint2*)(brow + dbase);
        const unsigned char* bp = (const unsigned char*)&bb;
        float4 w0 = *(const float4*)(w + i);
        float4 w1 = *(const float4*)(w + i + 4);
        float4 n0 = *(const float4*)(wn + i);
        float4 n1 = *(const float4*)(wn + i + 4);
        float wv[8] = {w0.x, w0.y, w0.z, w0.w, w1.x, w1.y, w1.z, w1.w};
        float nv[8] = {n0.x, n0.y, n0.z, n0.w, n1.x, n1.y, n1.z, n1.w};
        __align__(16) __half h[8];
        #pragma unroll
        for (int j = 0; j < 8; ++j) {
            const float mj = (gate && bp[j]) ? 1.0f : 0.0f;
            h[j] = __float2half(fmaf(mj, nv[j], wv[j]));
        }
        *(uint4*)(g_wh + i) = *(uint4*)h;
    }
}

// ---------------------------------------------------------------------------
// K4: fp16 GEMM via mma.sync (HMMA), fp32 accumulate
//     CTA 128x128, 4 warps of 64x64 (square warp tile: 128 B smem / MMA),
//     KC=64, 3-stage cp.async pipeline, 2 CTAs/SM, double-buffered fragments.
// ---------------------------------------------------------------------------
#define KC        64
#define NITER     (D_ / KC)              // 64
#define TSTRIDE   144                    // 128B payload + 16B pad
#define TILE_B    (128 * TSTRIDE)        // 18432
#define T_A       0
#define T_B       TILE_B
#define STAGE_B   (2 * TILE_B)           // 36864
#define NSTAGE    3
#define SMEM_GEMM (NSTAGE * STAGE_B)     // 110592 (x2 CTAs = 221KB <= 228KB)

__device__ __forceinline__ void ldsm_x4(uint32_t* r, uint32_t addr)
{
    asm volatile("ldmatrix.sync.aligned.m8n8.x4.shared.b16 {%0,%1,%2,%3}, [%4];"
                 : "=r"(r[0]), "=r"(r[1]), "=r"(r[2]), "=r"(r[3]) : "r"(addr));
}

__device__ __forceinline__ void mma16816(float* d, const uint32_t* a, const uint32_t* b)
{
    asm volatile("mma.sync.aligned.m16n8k16.row.col.f32.f16.f16.f32 "
                 "{%0,%1,%2,%3}, {%4,%5,%6,%7}, {%8,%9}, {%0,%1,%2,%3};"
                 : "+f"(d[0]), "+f"(d[1]), "+f"(d[2]), "+f"(d[3])
                 : "r"(a[0]), "r"(a[1]), "r"(a[2]), "r"(a[3]), "r"(b[0]), "r"(b[1]));
}

__device__ __forceinline__ void cp16(uint32_t dst, const void* src)
{
    asm volatile("cp.async.cg.shared.global [%0], [%1], 16;" :: "r"(dst), "l"(src));
}

// 128 threads stage a 128-row x 64-half tile (8 cp16 per thread)
__device__ __forceinline__ void stage_tile(uint32_t sdst, const __half* __restrict__ src,
                                           int row0, int k0)
{
    const int tid = threadIdx.x;
    #pragma unroll
    for (int j = 0; j < 8; ++j) {
        int c   = tid + j * 128;        // 0..1023
        int row = c >> 3;
        int col = c & 7;                // 16B chunk within 128B row payload
        cp16(sdst + row * TSTRIDE + col * 16,
             src + (size_t)(row0 + row) * D_ + k0 + col * 8);
    }
}

__device__ __forceinline__ void stage_all(uint32_t st, int bm, int bn, int k0)
{
    stage_tile(st + T_A, g_xh, bm, k0);
    stage_tile(st + T_B, g_wh, bn, k0);
    asm volatile("cp.async.commit_group;" ::: "memory");
}

// load B fragments for one kk: 4 ldsm.x4 -> 8 n8 fragments
__device__ __forceinline__ void load_bfrags(uint32_t (*bf)[2], uint32_t base)
{
    #pragma unroll
    for (int g = 0; g < 4; ++g) {
        uint32_t r[4];
        ldsm_x4(r, base + (uint32_t)(g * 16) * TSTRIDE);
        bf[2 * g][0]     = r[0]; bf[2 * g][1]     = r[2];
        bf[2 * g + 1][0] = r[1]; bf[2 * g + 1][1] = r[3];
    }
}

__global__ __launch_bounds__(128, 2) void gemm_kernel(float* __restrict__ C)
{
    extern __shared__ char smem[];
    uint32_t sbase;
    asm("{ .reg .u64 t; cvta.to.shared.u64 t, %1; cvt.u32.u64 %0, t; }"
        : "=r"(sbase) : "l"(smem));

    const int tid  = threadIdx.x;
    const int wid  = tid >> 5;
    const int lane = tid & 31;
    const int wm   = wid & 1;          // 2 warps along M
    const int wn   = wid >> 1;         // 2 warps along N
    const int bm   = blockIdx.y * 128;
    const int bn   = blockIdx.x * 128;

    float acc[4][8][4];
    #pragma unroll
    for (int i = 0; i < 4; ++i)
        #pragma unroll
        for (int j = 0; j < 8; ++j)
            #pragma unroll
            for (int e = 0; e < 4; ++e) acc[i][j][e] = 0.f;

    const uint32_t lrow  = (uint32_t)(lane & 15);
    const uint32_t lkoff = (uint32_t)((lane >> 4) * 16);

    const uint32_t aoff = T_A + ((uint32_t)(wm * 64) + lrow) * TSTRIDE + lkoff;
    const uint32_t boff = T_B + ((uint32_t)(wn * 64) + lrow) * TSTRIDE + lkoff;

    // prologue: stages 0, 1
    stage_all(sbase + 0 * STAGE_B, bm, bn, 0 * KC);
    stage_all(sbase + 1 * STAGE_B, bm, bn, 1 * KC);

    uint32_t cur = sbase;
    uint32_t fut = sbase + 2 * STAGE_B;

    for (int it = 0; it < NITER; ++it) {
        asm volatile("cp.async.wait_group 1;" ::: "memory");
        __syncthreads();   // slot `cur` visible; slot `fut` free for refill

        uint32_t a[2][4][4], bf[2][8][2];

        // fragment prologue: kk = 0 into buffer 0
        load_bfrags(bf[0], cur + boff);
        #pragma unroll
        for (int mt = 0; mt < 4; ++mt)
            ldsm_x4(a[0][mt], cur + aoff + (uint32_t)(mt * 16) * TSTRIDE);

        // next-stage cp.async under fragment loads
        if (it + 2 < NITER) {
            stage_all(fut, bm, bn, (it + 2) * KC);
        } else {
            asm volatile("cp.async.commit_group;" ::: "memory");  // keep counts
        }

        #pragma unroll
        for (int kk = 0; kk < 4; ++kk) {
            const int cb = kk & 1, nb = cb ^ 1;

            if (kk < 3) {   // prefetch kk+1 fragments under this kk's 32 MMAs
                const uint32_t kb = (uint32_t)((kk + 1) * 32);
                load_bfrags(bf[nb], cur + boff + kb);
                #pragma unroll
                for (int mt = 0; mt < 4; ++mt)
                    ldsm_x4(a[nb][mt], cur + aoff + (uint32_t)(mt * 16) * TSTRIDE + kb);
            }

            #pragma unroll
            for (int mt = 0; mt < 4; ++mt)
                #pragma unroll
                for (int nt = 0; nt < 8; ++nt)
                    mma16816(acc[mt][nt], a[cb][mt], bf[cb][nt]);
        }

        const uint32_t top = sbase + 2 * STAGE_B;
        cur = (cur == top) ? sbase : cur + STAGE_B;
        fut = (fut == top) ? sbase : fut + STAGE_B;
    }

    // Epilogue: direct float2 stores
    const int er = lane >> 2;
    const int ec = (lane & 3) * 2;
    #pragma unroll
    for (int mt = 0; mt < 4; ++mt) {
        const int row = bm + wm * 64 + mt * 16 + er;
        #pragma unroll
        for (int nt = 0; nt < 8; ++nt) {
            const int col = bn + wn * 64 + nt * 8 + ec;
            *(float2*)(C + (size_t)row * O_ + col) =
                make_float2(acc[mt][nt][0], acc[mt][nt][1]);
            *(float2*)(C + (size_t)(row + 8) * O_ + col) =
                make_float2(acc[mt][nt][2], acc[mt][nt][3]);
        }
    }
}

// ---------------------------------------------------------------------------
extern "C" void kernel_launch(void* const* d_in, const int* in_sizes, int n_in,
                              void* d_out, int out_size)
{
    const float*         x      = (const float*)d_in[0];
    const float*         w      = (const float*)d_in[1];
    const float*         wn     = (const float*)d_in[2];
    const int*           perm   = (const int*)d_in[3];
    const unsigned char* stored = (const unsigned char*)d_in[4];
    const int*           pb     = (const int*)d_in[5];
    float*               out    = (float*)d_out;

    (void)in_sizes; (void)n_in; (void)out_size;

    static bool attr_set = false;
    if (!attr_set) {
        cudaFuncSetAttribute(gemm_kernel, cudaFuncAttributeMaxDynamicSharedMemorySize,
                             SMEM_GEMM);
        attr_set = true;
    }

    mean_p1<<<dim3(32, 8), 128>>>(x, pb);                      // 0
    rank_kernel<<<32, 512>>>(perm, pb, stored);                // 1
    split_kernel<<<XBLKS_ + WBLKS_, 256>>>(x, w, wn, stored);  // 2
    dim3 grid(O_ / 128, M_ / 128);
    gemm_kernel<<<grid, 128, SMEM_GEMM>>>(out);                // 3 <- ncu slot
}

// round 13
// speedup vs baseline: 1.0022x; 1.0022x over previous
#include <cuda_runtime.h>
#include <cuda_bf16.h>
#include <cuda_fp16.h>
#include <cstdint>

// Problem dims (fixed by the reference)
#define B_      4
#define S_      2048
#define D_      4096
#define O_      4096
#define M_      8192
#define TOPK_   2048
#define NMASKS_ 100

// ---------------------------------------------------------------------------
// Static device scratch (no runtime allocation allowed)
// ---------------------------------------------------------------------------
__device__ float g_psum[8][D_];
__device__ unsigned char g_amask[D_];
__device__ int g_counts[NMASKS_];
__device__ __align__(16) __half g_xh[(size_t)M_ * D_];   // fp16(x)
__device__ __align__(16) __half g_wh[(size_t)O_ * D_];   // fp16(weff)

// ---------------------------------------------------------------------------
// K1: partial column sums of x[0, 0..pb, :] over 8 row chunks
// grid (32, 8), 128 threads. y==0 zeroes g_amask; (0,0) zeroes g_counts.
// ---------------------------------------------------------------------------
__global__ void mean_p1(const float* __restrict__ x, const int* __restrict__ pb)
{
    const int d = blockIdx.x * 128 + threadIdx.x;
    if (blockIdx.y == 0) {
        g_amask[d] = 0;
        if (blockIdx.x == 0 && threadIdx.x < NMASKS_) g_counts[threadIdx.x] = 0;
    }
    const int rows  = pb[0] + 1;
    const int chunk = (rows + 7) / 8;
    const int r0 = blockIdx.y * chunk;
    const int r1 = (r0 + chunk < rows) ? (r0 + chunk) : rows;
    float s = 0.f;
    int r = r0;
    for (; r + 4 <= r1; r += 4) {
        s += x[(size_t)(r + 0) * D_ + d];
        s += x[(size_t)(r + 1) * D_ + d];
        s += x[(size_t)(r + 2) * D_ + d];
        s += x[(size_t)(r + 3) * D_ + d];
    }
    for (; r < r1; ++r) s += x[(size_t)r * D_ + d];
    g_psum[blockIdx.y][d] = s;
}

// ---------------------------------------------------------------------------
// K2: reduce partials -> f, exact top-k rank, scatter via perm, AND
//     accumulate per-block partial overlap counts into g_counts.
// 32 blocks x 512 threads.
// ---------------------------------------------------------------------------
__global__ void rank_kernel(const int* __restrict__ perm, const int* __restrict__ pb,
                            const unsigned char* __restrict__ stored)
{
    __shared__ unsigned int keys[D_];
    __shared__ int sr[128][4];
    __shared__ int spos[128];
    __shared__ int ssel[128];

    const int t = threadIdx.x;
    const int rows = pb[0] + 1;

    for (int j = t; j < D_; j += 512) {
        float s = 0.f;
        #pragma unroll
        for (int y = 0; y < 8; ++y) s += g_psum[y][j];
        keys[j] = __float_as_uint(fabsf(s / (float)rows));
    }
    __syncthreads();

    const int jl = t & 127;
    const int h  = t >> 7;                       // 0..3
    const int j  = blockIdx.x * 128 + jl;
    const unsigned int kj = keys[j];
    int r = 0;
    const int i0 = h * 1024;
    #pragma unroll 8
    for (int i = i0; i < i0 + 1024; ++i) {
        const unsigned int ki = keys[i];
        r += (ki > kj) || (ki == kj && i < j);
    }
    sr[jl][h] = r;
    __syncthreads();

    if (t < 128) {
        const int rank = sr[t][0] + sr[t][1] + sr[t][2] + sr[t][3];
        const int pos  = perm[blockIdx.x * 128 + t];
        const int sel  = (rank < TOPK_) ? 1 : 0;
        spos[t] = pos;
        ssel[t] = sel;
        if (sel) g_amask[pos] = 1;               // perm: no conflicts
    }
    __syncthreads();

    const int warp = t >> 5, lane = t & 31;
    for (int m = warp; m < NMASKS_; m += 16) {
        const unsigned char* row = stored + (size_t)m * D_;
        int c = 0;
        #pragma unroll
        for (int i = lane; i < 128; i += 32)
            c += ssel[i] ? (int)row[spos[i]] : 0;
        #pragma unroll
        for (int o = 16; o > 0; o >>= 1) c += __shfl_down_sync(0xffffffffu, c, o);
        if (lane == 0) atomicAdd(&g_counts[m], c);
    }
}

// ---------------------------------------------------------------------------
// K3 (merged): blocks [0, 16384)      -> x -> fp16
//              blocks [16384, 24576)  -> weff = w + gate*mask*wn -> fp16
// ---------------------------------------------------------------------------
#define XBLKS_ ((int)(((size_t)M_ * D_ / 8) / 256))   // 16384
#define WBLKS_ ((int)(((size_t)O_ * D_ / 8) / 256))   // 8192

__global__ void split_kernel(const float* __restrict__ x,
                             const float* __restrict__ w,
                             const float* __restrict__ wn,
                             const unsigned char* __restrict__ stored)
{
    if (blockIdx.x < XBLKS_) {
        size_t i = ((size_t)blockIdx.x * 256 + threadIdx.x) * 8;
        float4 v0 = *(const float4*)(x + i);
        float4 v1 = *(const float4*)(x + i + 4);
        float v[8] = {v0.x, v0.y, v0.z, v0.w, v1.x, v1.y, v1.z, v1.w};
        __align__(16) __half h[8];
        #pragma unroll
        for (int j = 0; j < 8; ++j) h[j] = __float2half(v[j]);
        *(uint4*)(g_xh + i) = *(uint4*)h;
    } else {
        __shared__ int smax[8];
        __shared__ int s_best;
        const int t = threadIdx.x;
        int v = 0;
        if (t < NMASKS_) v = (g_counts[t] << 7) | (127 - t);
        #pragma unroll
        for (int o = 16; o > 0; o >>= 1) v = max(v, __shfl_down_sync(0xffffffffu, v, o));
        if ((t & 31) == 0) smax[t >> 5] = v;
        __syncthreads();
        if (t == 0) {
            int b = smax[0];
            #pragma unroll
            for (int q = 1; q < 8; ++q) b = max(b, smax[q]);
            s_best = b;
        }
        __syncthreads();
        const int best = s_best;
        const int gate = ((best >> 7) >= 1229);   // count/2048 >= float32(0.6)
        const unsigned char* brow = stored + (size_t)(127 - (best & 127)) * D_;

        size_t i = ((size_t)(blockIdx.x - XBLKS_) * 256 + t) * 8;
        const int dbase = (int)(i & (size_t)(D_ - 1));
        uint2 bb = *(const uint2*)(brow + dbase);
        const unsigned char* bp = (const unsigned char*)&bb;
        float4 w0 = *(const float4*)(w + i);
        float4 w1 = *(const float4*)(w + i + 4);
        float4 n0 = *(const float4*)(wn + i);
        float4 n1 = *(const float4*)(wn + i + 4);
        float wv[8] = {w0.x, w0.y, w0.z, w0.w, w1.x, w1.y, w1.z, w1.w};
        float nv[8] = {n0.x, n0.y, n0.z, n0.w, n1.x, n1.y, n1.z, n1.w};
        __align__(16) __half h[8];
        #pragma unroll
        for (int j = 0; j < 8; ++j) {
            const float mj = (gate && bp[j]) ? 1.0f : 0.0f;
            h[j] = __float2half(fmaf(mj, nv[j], wv[j]));
        }
        *(uint4*)(g_wh + i) = *(uint4*)h;
    }
}

// ---------------------------------------------------------------------------
// K4: fp16 GEMM via mma.sync (HMMA), fp32 accumulate — persistent CTAs.
//     296 CTAs (one wave, 2/SM). Each CTA walks tiles c, c+296, ... with a
//     FLAT cp.async pipeline across tile boundaries: stage(g+2) is issued
//     even when it belongs to the next tile, so the next tile's prologue DMA
//     and this tile's epilogue stores overlap.
//     Per tile: 128x128, 8 warps of 64x32, KC=64, 3 smem slots,
//     double-buffered fragments (R11 config).
// ---------------------------------------------------------------------------
#define KC        64
#define NITER     (D_ / KC)              // 64
#define NTILES    2048
#define NCTA      296
#define TSTRIDE   144                    // 128B payload + 16B pad
#define TILE_B    (128 * TSTRIDE)        // 18432
#define T_A       0
#define T_B       TILE_B
#define STAGE_B   (2 * TILE_B)           // 36864
#define SMEM_GEMM (3 * STAGE_B)          // 110592 (x2 CTAs = 221KB <= 228KB)

__device__ __forceinline__ void ldsm_x4(uint32_t* r, uint32_t addr)
{
    asm volatile("ldmatrix.sync.aligned.m8n8.x4.shared.b16 {%0,%1,%2,%3}, [%4];"
                 : "=r"(r[0]), "=r"(r[1]), "=r"(r[2]), "=r"(r[3]) : "r"(addr));
}

__device__ __forceinline__ void mma16816(float* d, const uint32_t* a, const uint32_t* b)
{
    asm volatile("mma.sync.aligned.m16n8k16.row.col.f32.f16.f16.f32 "
                 "{%0,%1,%2,%3}, {%4,%5,%6,%7}, {%8,%9}, {%0,%1,%2,%3};"
                 : "+f"(d[0]), "+f"(d[1]), "+f"(d[2]), "+f"(d[3])
                 : "r"(a[0]), "r"(a[1]), "r"(a[2]), "r"(a[3]), "r"(b[0]), "r"(b[1]));
}

__device__ __forceinline__ void cp16(uint32_t dst, const void* src)
{
    asm volatile("cp.async.cg.shared.global [%0], [%1], 16;" :: "r"(dst), "l"(src));
}

__device__ __forceinline__ void stage_tile(uint32_t sdst, const __half* __restrict__ src,
                                           int row0, int k0)
{
    const int tid = threadIdx.x;
    #pragma unroll
    for (int j = 0; j < 2; ++j) {
        int c   = tid + j * 256;        // 0..511
        int row = c >> 2;
        int col = c & 3;                // 32B chunks? no: 4x16B = 64B... (see below)
        // 128B payload per row = 8 x 16B; 512 thread-chunks cover 128 rows x 4,
        // so each thread does 2 chunks here and stage_tile is called with the
        // second half offset pattern below.
        (void)row; (void)col;
        break;
    }
    // 128 rows x 8 chunks of 16B = 1024 chunks, 256 threads -> 4 per thread
    #pragma unroll
    for (int j = 0; j < 4; ++j) {
        int c   = tid + j * 256;        // 0..1023
        int row = c >> 3;
        int col = c & 7;                // 16B chunk within 128B row payload
        cp16(sdst + row * TSTRIDE + col * 16,
             src + (size_t)(row0 + row) * D_ + k0 + col * 8);
    }
}

__device__ __forceinline__ void stage_all(uint32_t st, int bm, int bn, int k0)
{
    stage_tile(st + T_A, g_xh, bm, k0);
    stage_tile(st + T_B, g_wh, bn, k0);
    asm volatile("cp.async.commit_group;" ::: "memory");
}

__global__ __launch_bounds__(256, 2) void gemm_kernel(float* __restrict__ C)
{
    extern __shared__ char smem[];
    uint32_t sbase;
    asm("{ .reg .u64 t; cvta.to.shared.u64 t, %1; cvt.u32.u64 %0, t; }"
        : "=r"(sbase) : "l"(smem));

    const int tid  = threadIdx.x;
    const int wid  = tid >> 5;
    const int lane = tid & 31;
    const int wm   = wid & 1;          // 2 warps along M
    const int wn   = wid >> 1;         // 4 warps along N
    const int cta  = blockIdx.x;

    const int my_ntiles = (NTILES - cta + NCTA - 1) / NCTA;   // 6 or 7
    const int total_g   = my_ntiles * NITER;

    float acc[4][4][4];
    #pragma unroll
    for (int i = 0; i < 4; ++i)
        #pragma unroll
        for (int j = 0; j < 4; ++j)
            #pragma unroll
            for (int e = 0; e < 4; ++e) acc[i][j][e] = 0.f;

    const uint32_t lrow  = (uint32_t)(lane & 15);
    const uint32_t lkoff = (uint32_t)((lane >> 4) * 16);
    const uint32_t aoff  = T_A + ((uint32_t)(wm * 64) + lrow) * TSTRIDE + lkoff;
    const uint32_t boff  = T_B + ((uint32_t)(wn * 32) + lrow) * TSTRIDE + lkoff;

    // prologue: stages for g = 0, 1 (both in tile 0 of this CTA)
    {
        const int bm0 = (cta >> 5) * 128;
        const int bn0 = (cta & 31) * 128;
        stage_all(sbase + 0 * STAGE_B, bm0, bn0, 0 * KC);
        stage_all(sbase + 1 * STAGE_B, bm0, bn0, 1 * KC);
    }

    uint32_t cur = sbase;                          // slot g % 3

    for (int g = 0; g < total_g; ++g) {
        asm volatile("cp.async.wait_group 1;" ::: "memory");
        __syncthreads();   // slot `cur` visible everywhere; slot (g+2)%3 free

        uint32_t a[2][4][4], bf[2][4][2];

        // fragment prologue: kk = 0 into buffer 0
        {
            uint32_t r0[4], r1[4];
            ldsm_x4(r0, cur + boff);
            #pragma unroll
            for (int mt = 0; mt < 4; ++mt)
                ldsm_x4(a[0][mt], cur + aoff + (uint32_t)(mt * 16) * TSTRIDE);
            ldsm_x4(r1, cur + boff + 16 * TSTRIDE);
            bf[0][0][0] = r0[0]; bf[0][0][1] = r0[2];
            bf[0][1][0] = r0[1]; bf[0][1][1] = r0[3];
            bf[0][2][0] = r1[0]; bf[0][2][1] = r1[2];
            bf[0][3][0] = r1[1]; bf[0][3][1] = r1[3];
        }

        // stage g+2 (possibly the NEXT tile's first chunks) under frag loads
        {
            const int gs = g + 2;
            if (gs < total_g) {
                const int ts   = gs >> 6;                 // tile index (local)
                const int tidx = cta + NCTA * ts;         // global tile id
                const int bms  = (tidx >> 5) * 128;
                const int bns  = (tidx & 31) * 128;
                uint32_t fut = sbase + (uint32_t)(((uint32_t)gs) % 3u) * STAGE_B;
                stage_all(fut, bms, bns, (gs & 63) * KC);
            } else {
                asm volatile("cp.async.commit_group;" ::: "memory");  // keep counts
            }
        }

        #pragma unroll
        for (int kk = 0; kk < 4; ++kk) {
            const int cb = kk & 1, nb = cb ^ 1;

            if (kk < 3) {   // prefetch kk+1 fragments under this kk's MMAs
                const uint32_t kb = (uint32_t)((kk + 1) * 32);
                uint32_t r0[4], r1[4];
                ldsm_x4(r0, cur + boff + kb);
                #pragma unroll
                for (int mt = 0; mt < 4; ++mt)
                    ldsm_x4(a[nb][mt], cur + aoff + (uint32_t)(mt * 16) * TSTRIDE + kb);
                ldsm_x4(r1, cur + boff + 16 * TSTRIDE + kb);
                bf[nb][0][0] = r0[0]; bf[nb][0][1] = r0[2];
                bf[nb][1][0] = r0[1]; bf[nb][1][1] = r0[3];
                bf[nb][2][0] = r1[0]; bf[nb][2][1] = r1[2];
                bf[nb][3][0] = r1[1]; bf[nb][3][1] = r1[3];
            }

            #pragma unroll
            for (int mt = 0; mt < 4; ++mt)
                #pragma unroll
                for (int nt = 0; nt < 4; ++nt)
                    mma16816(acc[mt][nt], a[cb][mt], bf[cb][nt]);
        }

        // tile epilogue: runs AFTER next tile's prologue DMA was issued,
        // so STGs overlap the in-flight cp.async.
        if ((g & 63) == 63) {
            const int tidx = cta + NCTA * (g >> 6);
            const int bm = (tidx >> 5) * 128;
            const int bn = (tidx & 31) * 128;
            const int er = lane >> 2;
            const int ec = (lane & 3) * 2;
            #pragma unroll
            for (int mt = 0; mt < 4; ++mt) {
                const int row = bm + wm * 64 + mt * 16 + er;
                #pragma unroll
                for (int nt = 0; nt < 4; ++nt) {
                    const int col = bn + wn * 32 + nt * 8 + ec;
                    *(float2*)(C + (size_t)row * O_ + col) =
                        make_float2(acc[mt][nt][0], acc[mt][nt][1]);
                    *(float2*)(C + (size_t)(row + 8) * O_ + col) =
                        make_float2(acc[mt][nt][2], acc[mt][nt][3]);
                    acc[mt][nt][0] = 0.f; acc[mt][nt][1] = 0.f;
                    acc[mt][nt][2] = 0.f; acc[mt][nt][3] = 0.f;
                }
            }
        }

        const uint32_t top = sbase + 2 * STAGE_B;
        cur = (cur == top) ? sbase : cur + STAGE_B;
    }
}

// ---------------------------------------------------------------------------
extern "C" void kernel_launch(void* const* d_in, const int* in_sizes, int n_in,
                              void* d_out, int out_size)
{
    const float*         x      = (const float*)d_in[0];
    const float*         w      = (const float*)d_in[1];
    const float*         wn     = (const float*)d_in[2];
    const int*           perm   = (const int*)d_in[3];
    const unsigned char* stored = (const unsigned char*)d_in[4];
    const int*           pb     = (const int*)d_in[5];
    float*               out    = (float*)d_out;

    (void)in_sizes; (void)n_in; (void)out_size;

    static bool attr_set = false;
    if (!attr_set) {
        cudaFuncSetAttribute(gemm_kernel, cudaFuncAttributeMaxDynamicSharedMemorySize,
                             SMEM_GEMM);
        attr_set = true;
    }

    mean_p1<<<dim3(32, 8), 128>>>(x, pb);                      // 0
    rank_kernel<<<32, 512>>>(perm, pb, stored);                // 1
    split_kernel<<<XBLKS_ + WBLKS_, 256>>>(x, w, wn, stored);  // 2
    gemm_kernel<<<NCTA, 256, SMEM_GEMM>>>(out);                // 3 <- ncu slot
}

// round 14
// speedup vs baseline: 1.0667x; 1.0644x over previous
#include <cuda_runtime.h>
#include <cuda_bf16.h>
#include <cuda_fp16.h>
#include <cstdint>

// Problem dims (fixed by the reference)
#define B_      4
#define S_      2048
#define D_      4096
#define O_      4096
#define M_      8192
#define TOPK_   2048
#define NMASKS_ 100

// ---------------------------------------------------------------------------
// Static device scratch (no runtime allocation allowed)
// ---------------------------------------------------------------------------
__device__ float g_psum[8][D_];
__device__ unsigned char g_amask[D_];
__device__ int g_counts[NMASKS_];
__device__ __align__(16) __half g_xh[(size_t)M_ * D_];   // fp16(x)
__device__ __align__(16) __half g_wh[(size_t)O_ * D_];   // fp16(weff)

// ---------------------------------------------------------------------------
// K1: partial column sums of x[0, 0..pb, :] over 8 row chunks
// grid (32, 8), 128 threads. y==0 zeroes g_amask; (0,0) zeroes g_counts.
// ---------------------------------------------------------------------------
__global__ void mean_p1(const float* __restrict__ x, const int* __restrict__ pb)
{
    const int d = blockIdx.x * 128 + threadIdx.x;
    if (blockIdx.y == 0) {
        g_amask[d] = 0;
        if (blockIdx.x == 0 && threadIdx.x < NMASKS_) g_counts[threadIdx.x] = 0;
    }
    const int rows  = pb[0] + 1;
    const int chunk = (rows + 7) / 8;
    const int r0 = blockIdx.y * chunk;
    const int r1 = (r0 + chunk < rows) ? (r0 + chunk) : rows;
    float s = 0.f;
    int r = r0;
    for (; r + 4 <= r1; r += 4) {
        s += x[(size_t)(r + 0) * D_ + d];
        s += x[(size_t)(r + 1) * D_ + d];
        s += x[(size_t)(r + 2) * D_ + d];
        s += x[(size_t)(r + 3) * D_ + d];
    }
    for (; r < r1; ++r) s += x[(size_t)r * D_ + d];
    g_psum[blockIdx.y][d] = s;
}

// ---------------------------------------------------------------------------
// K2 (merged, 512 threads):
//   blocks [0, 32)      : reduce partials -> f, exact top-k rank, scatter via
//                         perm, partial overlap counts -> g_counts
//   blocks [32, 8224)   : x -> fp16 (8 elems/thread, 512 threads)
// The two halves are data-independent and run concurrently on the device.
// ---------------------------------------------------------------------------
#define RBLKS_  32
#define XBLKS_ ((int)(((size_t)M_ * D_ / 8) / 512))   // 8192
#define WBLKS_ ((int)(((size_t)O_ * D_ / 8) / 256))   // 8192

__global__ __launch_bounds__(512) void rank_splitx_kernel(
    const int* __restrict__ perm, const int* __restrict__ pb,
    const unsigned char* __restrict__ stored, const float* __restrict__ x)
{
    const int t = threadIdx.x;

    if (blockIdx.x >= RBLKS_) {
        // ---- split-X half ----
        size_t i = (((size_t)(blockIdx.x - RBLKS_) * 512) + t) * 8;
        float4 v0 = *(const float4*)(x + i);
        float4 v1 = *(const float4*)(x + i + 4);
        float v[8] = {v0.x, v0.y, v0.z, v0.w, v1.x, v1.y, v1.z, v1.w};
        __align__(16) __half h[8];
        #pragma unroll
        for (int j = 0; j < 8; ++j) h[j] = __float2half(v[j]);
        *(uint4*)(g_xh + i) = *(uint4*)h;
        return;
    }

    // ---- rank half ----
    __shared__ unsigned int keys[D_];
    __shared__ int sr[128][4];
    __shared__ int spos[128];
    __shared__ int ssel[128];

    const int rows = pb[0] + 1;
    for (int j = t; j < D_; j += 512) {
        float s = 0.f;
        #pragma unroll
        for (int y = 0; y < 8; ++y) s += g_psum[y][j];
        keys[j] = __float_as_uint(fabsf(s / (float)rows));
    }
    __syncthreads();

    const int jl = t & 127;
    const int h  = t >> 7;                       // 0..3
    const int j  = blockIdx.x * 128 + jl;
    const unsigned int kj = keys[j];
    int r = 0;
    const int i0 = h * 1024;
    #pragma unroll 8
    for (int i = i0; i < i0 + 1024; ++i) {
        const unsigned int ki = keys[i];
        r += (ki > kj) || (ki == kj && i < j);
    }
    sr[jl][h] = r;
    __syncthreads();

    if (t < 128) {
        const int rank = sr[t][0] + sr[t][1] + sr[t][2] + sr[t][3];
        const int pos  = perm[blockIdx.x * 128 + t];
        const int sel  = (rank < TOPK_) ? 1 : 0;
        spos[t] = pos;
        ssel[t] = sel;
        if (sel) g_amask[pos] = 1;               // perm: no conflicts
    }
    __syncthreads();

    const int warp = t >> 5, lane = t & 31;
    for (int m = warp; m < NMASKS_; m += 16) {
        const unsigned char* row = stored + (size_t)m * D_;
        int c = 0;
        #pragma unroll
        for (int i = lane; i < 128; i += 32)
            c += ssel[i] ? (int)row[spos[i]] : 0;
        #pragma unroll
        for (int o = 16; o > 0; o >>= 1) c += __shfl_down_sync(0xffffffffu, c, o);
        if (lane == 0) atomicAdd(&g_counts[m], c);
    }
}

// ---------------------------------------------------------------------------
// K3: weff = w + gate*mask*wn -> fp16 (argmax/gate from g_counts per block)
// ---------------------------------------------------------------------------
__global__ void splitw_kernel(const float* __restrict__ w,
                              const float* __restrict__ wn,
                              const unsigned char* __restrict__ stored)
{
    __shared__ int smax[8];
    __shared__ int s_best;
    const int t = threadIdx.x;
    int v = 0;
    if (t < NMASKS_) v = (g_counts[t] << 7) | (127 - t);
    #pragma unroll
    for (int o = 16; o > 0; o >>= 1) v = max(v, __shfl_down_sync(0xffffffffu, v, o));
    if ((t & 31) == 0) smax[t >> 5] = v;
    __syncthreads();
    if (t == 0) {
        int b = smax[0];
        #pragma unroll
        for (int q = 1; q < 8; ++q) b = max(b, smax[q]);
        s_best = b;
    }
    __syncthreads();
    const int best = s_best;
    const int gate = ((best >> 7) >= 1229);   // count/2048 >= float32(0.6)
    const unsigned char* brow = stored + (size_t)(127 - (best & 127)) * D_;

    size_t i = ((size_t)blockIdx.x * 256 + t) * 8;
    const int dbase = (int)(i & (size_t)(D_ - 1));
    uint2 bb = *(const uint2*)(brow + dbase);
    const unsigned char* bp = (const unsigned char*)&bb;
    float4 w0 = *(const float4*)(w + i);
    float4 w1 = *(const float4*)(w + i + 4);
    float4 n0 = *(const float4*)(wn + i);
    float4 n1 = *(const float4*)(wn + i + 4);
    float wv[8] = {w0.x, w0.y, w0.z, w0.w, w1.x, w1.y, w1.z, w1.w};
    float nv[8] = {n0.x, n0.y, n0.z, n0.w, n1.x, n1.y, n1.z, n1.w};
    __align__(16) __half h[8];
    #pragma unroll
    for (int j = 0; j < 8; ++j) {
        const float mj = (gate && bp[j]) ? 1.0f : 0.0f;
        h[j] = __float2half(fmaf(mj, nv[j], wv[j]));
    }
    *(uint4*)(g_wh + i) = *(uint4*)h;
}

// ---------------------------------------------------------------------------
// K4: fp16 GEMM via mma.sync (HMMA), fp32 accumulate  — R11 config (proven)
//     128x128 CTA tile, 8 warps of 64x32, KC=64, 3-stage cp.async pipeline,
//     2 CTAs/SM, double-buffered fragments (LDSM kk+1 under MMA kk).
// ---------------------------------------------------------------------------
#define KC        64
#define NITER     (D_ / KC)              // 64
#define TSTRIDE   144                    // 128B payload + 16B pad
#define TILE_B    (128 * TSTRIDE)        // 18432
#define T_A       0
#define T_B       TILE_B
#define STAGE_B   (2 * TILE_B)           // 36864
#define NSTAGE    3
#define SMEM_GEMM (NSTAGE * STAGE_B)     // 110592 (x2 CTAs = 221KB <= 228KB)

__device__ __forceinline__ void ldsm_x4(uint32_t* r, uint32_t addr)
{
    asm volatile("ldmatrix.sync.aligned.m8n8.x4.shared.b16 {%0,%1,%2,%3}, [%4];"
                 : "=r"(r[0]), "=r"(r[1]), "=r"(r[2]), "=r"(r[3]) : "r"(addr));
}

__device__ __forceinline__ void mma16816(float* d, const uint32_t* a, const uint32_t* b)
{
    asm volatile("mma.sync.aligned.m16n8k16.row.col.f32.f16.f16.f32 "
                 "{%0,%1,%2,%3}, {%4,%5,%6,%7}, {%8,%9}, {%0,%1,%2,%3};"
                 : "+f"(d[0]), "+f"(d[1]), "+f"(d[2]), "+f"(d[3])
                 : "r"(a[0]), "r"(a[1]), "r"(a[2]), "r"(a[3]), "r"(b[0]), "r"(b[1]));
}

__device__ __forceinline__ void cp16(uint32_t dst, const void* src)
{
    asm volatile("cp.async.cg.shared.global [%0], [%1], 16;" :: "r"(dst), "l"(src));
}

__device__ __forceinline__ void stage_tile(uint32_t sdst, const __half* __restrict__ src,
                                           int row0, int k0)
{
    const int tid = threadIdx.x;
    #pragma unroll
    for (int j = 0; j < 4; ++j) {
        int c   = tid + j * 256;        // 0..1023
        int row = c >> 3;
        int col = c & 7;                // 16B chunk within 128B row payload
        cp16(sdst + row * TSTRIDE + col * 16,
             src + (size_t)(row0 + row) * D_ + k0 + col * 8);
    }
}

__device__ __forceinline__ void stage_all(uint32_t st, int bm, int bn, int k0)
{
    stage_tile(st + T_A, g_xh, bm, k0);
    stage_tile(st + T_B, g_wh, bn, k0);
    asm volatile("cp.async.commit_group;" ::: "memory");
}

__global__ __launch_bounds__(256, 2) void gemm_kernel(float* __restrict__ C)
{
    extern __shared__ char smem[];
    uint32_t sbase;
    asm("{ .reg .u64 t; cvta.to.shared.u64 t, %1; cvt.u32.u64 %0, t; }"
        : "=r"(sbase) : "l"(smem));

    const int tid  = threadIdx.x;
    const int wid  = tid >> 5;
    const int lane = tid & 31;
    const int wm   = wid & 1;          // 2 warps along M
    const int wn   = wid >> 1;         // 4 warps along N
    const int bm   = blockIdx.y * 128;
    const int bn   = blockIdx.x * 128;

    float acc[4][4][4];
    #pragma unroll
    for (int i = 0; i < 4; ++i)
        #pragma unroll
        for (int j = 0; j < 4; ++j)
            #pragma unroll
            for (int e = 0; e < 4; ++e) acc[i][j][e] = 0.f;

    const uint32_t lrow  = (uint32_t)(lane & 15);
    const uint32_t lkoff = (uint32_t)((lane >> 4) * 16);

    const uint32_t aoff = T_A + ((uint32_t)(wm * 64) + lrow) * TSTRIDE + lkoff;
    const uint32_t boff = T_B + ((uint32_t)(wn * 32) + lrow) * TSTRIDE + lkoff;

    // prologue: stages 0, 1
    stage_all(sbase + 0 * STAGE_B, bm, bn, 0 * KC);
    stage_all(sbase + 1 * STAGE_B, bm, bn, 1 * KC);

    uint32_t cur = sbase;                    // slot it % 3
    uint32_t fut = sbase + 2 * STAGE_B;      // slot (it+2) % 3

    for (int it = 0; it < NITER; ++it) {
        asm volatile("cp.async.wait_group 1;" ::: "memory");
        __syncthreads();   // slot `cur` visible everywhere; slot `fut` free

        uint32_t a[2][4][4], bf[2][4][2];

        // fragment prologue: kk = 0 into buffer 0
        {
            uint32_t r0[4], r1[4];
            ldsm_x4(r0, cur + boff);
            #pragma unroll
            for (int mt = 0; mt < 4; ++mt)
                ldsm_x4(a[0][mt], cur + aoff + (uint32_t)(mt * 16) * TSTRIDE);
            ldsm_x4(r1, cur + boff + 16 * TSTRIDE);
            bf[0][0][0] = r0[0]; bf[0][0][1] = r0[2];
            bf[0][1][0] = r0[1]; bf[0][1][1] = r0[3];
            bf[0][2][0] = r1[0]; bf[0][2][1] = r1[2];
            bf[0][3][0] = r1[1]; bf[0][3][1] = r1[3];
        }

        // issue next-stage cp.async under the first fragment loads
        if (it + 2 < NITER) {
            stage_all(fut, bm, bn, (it + 2) * KC);
        } else {
            asm volatile("cp.async.commit_group;" ::: "memory");  // keep counts
        }

        #pragma unroll
        for (int kk = 0; kk < 4; ++kk) {
            const int cb = kk & 1, nb = cb ^ 1;

            if (kk < 3) {   // prefetch kk+1 fragments under this kk's MMAs
                const uint32_t kb = (uint32_t)((kk + 1) * 32);
                uint32_t r0[4], r1[4];
                ldsm_x4(r0, cur + boff + kb);
                #pragma unroll
                for (int mt = 0; mt < 4; ++mt)
                    ldsm_x4(a[nb][mt], cur + aoff + (uint32_t)(mt * 16) * TSTRIDE + kb);
                ldsm_x4(r1, cur + boff + 16 * TSTRIDE + kb);
                bf[nb][0][0] = r0[0]; bf[nb][0][1] = r0[2];
                bf[nb][1][0] = r0[1]; bf[nb][1][1] = r0[3];
                bf[nb][2][0] = r1[0]; bf[nb][2][1] = r1[2];
                bf[nb][3][0] = r1[1]; bf[nb][3][1] = r1[3];
            }

            #pragma unroll
            for (int mt = 0; mt < 4; ++mt)
                #pragma unroll
                for (int nt = 0; nt < 4; ++nt)
                    mma16816(acc[mt][nt], a[cb][mt], bf[cb][nt]);
        }

        const uint32_t top = sbase + 2 * STAGE_B;
        cur = (cur == top) ? sbase : cur + STAGE_B;
        fut = (fut == top) ? sbase : fut + STAGE_B;
    }

    // Epilogue: direct float2 stores
    const int er = lane >> 2;
    const int ec = (lane & 3) * 2;
    #pragma unroll
    for (int mt = 0; mt < 4; ++mt) {
        const int row = bm + wm * 64 + mt * 16 + er;
        #pragma unroll
        for (int nt = 0; nt < 4; ++nt) {
            const int col = bn + wn * 32 + nt * 8 + ec;
            *(float2*)(C + (size_t)row * O_ + col) =
                make_float2(acc[mt][nt][0], acc[mt][nt][1]);
            *(float2*)(C + (size_t)(row + 8) * O_ + col) =
                make_float2(acc[mt][nt][2], acc[mt][nt][3]);
        }
    }
}

// ---------------------------------------------------------------------------
extern "C" void kernel_launch(void* const* d_in, const int* in_sizes, int n_in,
                              void* d_out, int out_size)
{
    const float*         x      = (const float*)d_in[0];
    const float*         w      = (const float*)d_in[1];
    const float*         wn     = (const float*)d_in[2];
    const int*           perm   = (const int*)d_in[3];
    const unsigned char* stored = (const unsigned char*)d_in[4];
    const int*           pb     = (const int*)d_in[5];
    float*               out    = (float*)d_out;

    (void)in_sizes; (void)n_in; (void)out_size;

    static bool attr_set = false;
    if (!attr_set) {
        cudaFuncSetAttribute(gemm_kernel, cudaFuncAttributeMaxDynamicSharedMemorySize,
                             SMEM_GEMM);
        attr_set = true;
    }

    mean_p1<<<dim3(32, 8), 128>>>(x, pb);                          // 0
    rank_splitx_kernel<<<RBLKS_ + XBLKS_, 512>>>(perm, pb, stored, x);  // 1
    splitw_kernel<<<WBLKS_, 256>>>(w, wn, stored);                 // 2
    dim3 grid(O_ / 128, M_ / 128);
    gemm_kernel<<<grid, 256, SMEM_GEMM>>>(out);                    // 3 <- ncu slot
}